// round 6
// baseline (speedup 1.0000x reference)
#include <cuda_runtime.h>
#include <math.h>
#include <stdint.h>

#define BB    128   // batch
#define TT    512   // timesteps
#define NNH   512   // hidden
#define NCOLT 16    // column tiles
#define NBT   8     // batch tiles
#define NCTA  128
#define NJ    32    // columns per CTA
#define MB    16    // batches per CTA
#define NTHR  256
#define WPf   516   // weight row pitch (floats)
#define CPf   516   // state row pitch (floats)

// -------- persistent device state --------
__device__ float g_c[2][NNH * BB];      // [n][b], double buffered
__device__ float g_h[2][NNH * BB];
__device__ unsigned int g_bar;

__global__ void hippo_init(const float* __restrict__ h0, const float* __restrict__ c0) {
    int idx = blockIdx.x * blockDim.x + threadIdx.x;
    if (idx == 0) g_bar = 0u;
    int total = NNH * BB;
    for (int i = idx; i < total; i += gridDim.x * blockDim.x) {
        int n = i / BB;
        int b = i % BB;
        g_c[0][i] = c0[b * NNH + n];
        g_h[0][i] = h0[b * NNH + n];
    }
}

__device__ __forceinline__ void bar_arrive() {
    __syncthreads();
    if (threadIdx.x == 0) {
        asm volatile("red.release.gpu.global.add.u32 [%0], 1;"
                     :: "l"(&g_bar) : "memory");
    }
}
__device__ __forceinline__ void bar_wait(unsigned int target) {
    if (threadIdx.x == 0) {
        unsigned int v;
        do {
            asm volatile("ld.acquire.gpu.global.u32 %0, [%1];"
                         : "=r"(v) : "l"(&g_bar) : "memory");
        } while (v < target);
    }
    __syncthreads();
}

__device__ __forceinline__ void fma2(uint64_t& d, uint64_t a, uint64_t b) {
    asm("fma.rn.f32x2 %0, %1, %2, %0;" : "+l"(d) : "l"(a), "l"(b));
}
__device__ __forceinline__ uint64_t pack2(float x, float y) {
    uint64_t r;
    asm("mov.b64 %0, {%1, %2};" : "=l"(r) : "f"(x), "f"(y));
    return r;
}
__device__ __forceinline__ float2 unpack2(uint64_t v) {
    float2 r;
    asm("mov.b64 {%0, %1}, %2;" : "=f"(r.x), "=f"(r.y) : "l"(v));
    return r;
}

// smem (floats): Wi[NJ*WPf] Wh[NJ*WPf] c[MB*CPf] h[MB*CPf] wf[512]
//                hs_tile[NJ*18] fredb[16*72] f_s[16] wx[NJ] bb[NJ]
#define SM_FLOATS (2 * NJ * WPf + 2 * MB * CPf + 512 + NJ * 18 + 16 * 72 + 16 + 2 * NJ)
#define SM_BYTES  (SM_FLOATS * 4)

__global__ __launch_bounds__(NTHR, 1) void hippo_persistent(
    const float* __restrict__ x,
    const float* __restrict__ Wi,
    const float* __restrict__ bi,
    const float* __restrict__ Wh,
    const float* __restrict__ bh,
    const float* __restrict__ Wf,
    const float* __restrict__ bfv,
    const float* __restrict__ A_stack,
    const float* __restrict__ B_stack,
    float* __restrict__ out)
{
    extern __shared__ float sm[];
    float* Wi_s  = sm;
    float* Wh_s  = Wi_s + NJ * WPf;
    float* c_s   = Wh_s + NJ * WPf;
    float* h_s   = c_s + MB * CPf;
    float* wf_s  = h_s + MB * CPf;      // 512 (all columns)
    float* hs_t  = wf_s + 512;          // NJ*18 transpose tile
    float* fredb = hs_t + NJ * 18;      // 16*72
    float* f_s   = fredb + 16 * 72;     // 16
    float* wx_s  = f_s + 16;            // NJ
    float* bb_s  = wx_s + NJ;           // NJ

    const int cta   = blockIdx.x;
    const int ct    = cta & (NCOLT - 1);
    const int bt    = cta >> 4;
    const int jbase = ct * NJ;
    const int bbase = bt * MB;
    const int tid   = threadIdx.x;
    const int j     = tid >> 3;          // 0..31
    const int bg    = tid & 7;           // 0..7
    const int b0    = bg;                // local batches bg, bg+8
    const int b1    = bg + 8;
    const int jg    = jbase + j;

    // ---- one-time loads ----
    for (int i = tid; i < NJ * NNH; i += NTHR) {
        int r = i >> 9, k = i & 511;
        Wi_s[r * WPf + k] = Wi[(jbase + r) * (NNH + 1) + 1 + k];
        Wh_s[r * WPf + k] = Wh[(jbase + r) * (NNH + 1) + 1 + k];
    }
    for (int i = tid; i < NNH; i += NTHR) wf_s[i] = Wf[1 + i];
    if (tid < NJ) {
        wx_s[tid] = Wi[(jbase + tid) * (NNH + 1)] + Wh[(jbase + tid) * (NNH + 1)];
        bb_s[tid] = bi[jbase + tid] + bh[jbase + tid];
    }
    // ---- initial state staging (k-major per batch) ----
    {
        const int q = tid & 3, n0 = tid >> 2;
        for (int it = 0; it < 8; ++it) {
            int n = n0 + 64 * it;
            float4 c4 = *(const float4*)(g_c[0] + n * BB + bbase + 4 * q);
            float4 h4 = *(const float4*)(g_h[0] + n * BB + bbase + 4 * q);
            c_s[(4 * q + 0) * CPf + n] = c4.x;  c_s[(4 * q + 1) * CPf + n] = c4.y;
            c_s[(4 * q + 2) * CPf + n] = c4.z;  c_s[(4 * q + 3) * CPf + n] = c4.w;
            h_s[(4 * q + 0) * CPf + n] = h4.x;  h_s[(4 * q + 1) * CPf + n] = h4.y;
            h_s[(4 * q + 2) * CPf + n] = h4.z;  h_s[(4 * q + 3) * CPf + n] = h4.w;
        }
    }
    __syncthreads();

    const float wf0 = Wf[0];
    const float bf0 = bfv[0];
    float* out_hs = out;
    float* out_cf = out + (size_t)BB * TT * NNH;

    const float* wiP = Wi_s + j * WPf;
    const float* whP = Wh_s + j * WPf;
    const float* cP0 = c_s + b0 * CPf;
    const float* cP1 = c_s + b1 * CPf;
    const float* hP0 = h_s + b0 * CPf;
    const float* hP1 = h_s + b1 * CPf;

    for (int t = 0; t < TT; ++t) {
        const int nxt = (t & 1) ^ 1;

        float xb0 = __ldcg(&x[(size_t)(bbase + b0) * TT + t]);
        float xb1 = __ldcg(&x[(size_t)(bbase + b1) * TT + t]);

        // ===== main k-loop: gates I/H + P = A_t·c, k-pair FMA2, no splats =====
        const float* Arow = A_stack + ((size_t)t * NNH + jg) * NNH;
        float4 ring[4];
        #pragma unroll
        for (int r = 0; r < 4; ++r)
            ring[r] = __ldg((const float4*)(Arow + 4 * r));

        uint64_t aI0 = 0, aI1 = 0, aH0 = 0, aH1 = 0, aP0 = 0, aP1 = 0;
        #pragma unroll 4
        for (int m = 0; m < 128; ++m) {
            const int k = 4 * m;
            float4 a4 = ring[m & 3];
            int kn = k + 16;
            if (kn >= NNH) kn = 0;                 // clamp (value unused)
            ring[m & 3] = __ldg((const float4*)(Arow + kn));

            ulonglong2 wi2 = *(const ulonglong2*)(wiP + k);
            ulonglong2 wh2 = *(const ulonglong2*)(whP + k);
            ulonglong2 cA  = *(const ulonglong2*)(cP0 + k);
            ulonglong2 cB  = *(const ulonglong2*)(cP1 + k);
            ulonglong2 hA  = *(const ulonglong2*)(hP0 + k);
            ulonglong2 hB  = *(const ulonglong2*)(hP1 + k);
            uint64_t aA = pack2(a4.x, a4.y);
            uint64_t aB = pack2(a4.z, a4.w);

            fma2(aI0, wi2.x, cA.x);  fma2(aI0, wi2.y, cA.y);
            fma2(aI1, wi2.x, cB.x);  fma2(aI1, wi2.y, cB.y);
            fma2(aH0, wh2.x, hA.x);  fma2(aH0, wh2.y, hA.y);
            fma2(aH1, wh2.x, hB.x);  fma2(aH1, wh2.y, hB.y);
            fma2(aP0, aA, cA.x);     fma2(aP0, aB, cA.y);
            fma2(aP1, aA, cB.x);     fma2(aP1, aB, cB.y);
        }

        // ===== epilogue: h_new =====
        float2 i0 = unpack2(aI0), i1 = unpack2(aI1);
        float2 hh0 = unpack2(aH0), hh1 = unpack2(aH1);
        float gate0 = i0.x + i0.y + hh0.x + hh0.y + bb_s[j] + wx_s[j] * xb0;
        float gate1 = i1.x + i1.y + hh1.x + hh1.y + bb_s[j] + wx_s[j] * xb1;
        float o0 = 1.f / (1.f + __expf(-gate0));
        float o1 = 1.f / (1.f + __expf(-gate1));
        float hn0 = o0 * tanhf(cP0[jg]);
        float hn1 = o1 * tanhf(cP1[jg]);
        g_h[nxt][jg * BB + bbase + b0] = hn0;
        g_h[nxt][jg * BB + bbase + b1] = hn1;
        hs_t[j * 18 + b0] = hn0;
        hs_t[j * 18 + b1] = hn1;
        __syncthreads();

        // coalesced hs output via transpose tile
        // 256 threads x float2 = 512 floats = 32 cols x 16 batches (exact tile)
        {
            int bo = tid >> 4;          // 0..15 batch
            int jq = tid & 15;          // 0..15 column pair
            float2 v;
            v.x = hs_t[(2 * jq + 0) * 18 + bo];
            v.y = hs_t[(2 * jq + 1) * 18 + bo];
            *(float2*)(out_hs + (size_t)(bbase + bo) * TT * NNH
                       + (size_t)t * NNH + jbase + 2 * jq) = v;
        }
        bar_arrive();                                // #1: h_new visible
        bar_wait((unsigned)(2 * t + 1) * NCTA);

        // ===== f computed locally from h (all columns, own batches) =====
        {
            const int q = tid & 3, n0 = tid >> 2;
            float fp0 = 0.f, fp1 = 0.f, fp2 = 0.f, fp3 = 0.f;
            #pragma unroll
            for (int it = 0; it < 8; ++it) {
                int n = n0 + 64 * it;
                float4 h4 = __ldcg((const float4*)(g_h[nxt] + n * BB + bbase + 4 * q));
                float w = wf_s[n];
                fp0 += w * h4.x;  fp1 += w * h4.y;
                fp2 += w * h4.z;  fp3 += w * h4.w;
            }
            fredb[(4 * q + 0) * 72 + n0] = fp0;
            fredb[(4 * q + 1) * 72 + n0] = fp1;
            fredb[(4 * q + 2) * 72 + n0] = fp2;
            fredb[(4 * q + 3) * 72 + n0] = fp3;
        }
        __syncthreads();
        if (tid < MB) {
            float s = 0.f;
            #pragma unroll
            for (int g4 = 0; g4 < 16; ++g4) {
                float4 v = *(const float4*)(fredb + tid * 72 + 4 * g4);
                s += v.x + v.y + v.z + v.w;
            }
            f_s[tid] = bf0 + wf0 * __ldcg(&x[(size_t)(bbase + tid) * TT + t]) + s;
        }
        __syncthreads();

        // ===== c_new =====
        {
            float Bt = __ldg(&B_stack[t * NNH + jg]);
            float2 p0v = unpack2(aP0), p1v = unpack2(aP1);
            float cn0 = p0v.x + p0v.y + f_s[b0] * Bt;
            float cn1 = p1v.x + p1v.y + f_s[b1] * Bt;
            g_c[nxt][jg * BB + bbase + b0] = cn0;
            g_c[nxt][jg * BB + bbase + b1] = cn1;
            if (t == TT - 1) {
                out_cf[(size_t)(bbase + b0) * NNH + jg] = cn0;
                out_cf[(size_t)(bbase + b1) * NNH + jg] = cn1;
            }
        }
        bar_arrive();                                // #2: c_new visible
        bar_wait((unsigned)(2 * t + 2) * NCTA);

        // ===== stage c,h (k-major transpose) for next step =====
        {
            const int q = tid & 3, n0 = tid >> 2;
            #pragma unroll
            for (int it = 0; it < 8; ++it) {
                int n = n0 + 64 * it;
                float4 c4 = __ldcg((const float4*)(g_c[nxt] + n * BB + bbase + 4 * q));
                float4 h4 = __ldcg((const float4*)(g_h[nxt] + n * BB + bbase + 4 * q));
                c_s[(4 * q + 0) * CPf + n] = c4.x;  c_s[(4 * q + 1) * CPf + n] = c4.y;
                c_s[(4 * q + 2) * CPf + n] = c4.z;  c_s[(4 * q + 3) * CPf + n] = c4.w;
                h_s[(4 * q + 0) * CPf + n] = h4.x;  h_s[(4 * q + 1) * CPf + n] = h4.y;
                h_s[(4 * q + 2) * CPf + n] = h4.z;  h_s[(4 * q + 3) * CPf + n] = h4.w;
            }
        }
        __syncthreads();
    }
}

extern "C" void kernel_launch(void* const* d_in, const int* in_sizes, int n_in,
                              void* d_out, int out_size) {
    const float* x   = (const float*)d_in[0];
    const float* h0  = (const float*)d_in[1];
    const float* c0  = (const float*)d_in[2];
    const float* Wi  = (const float*)d_in[3];
    const float* bi  = (const float*)d_in[4];
    const float* Wh  = (const float*)d_in[5];
    const float* bh  = (const float*)d_in[6];
    const float* Wf  = (const float*)d_in[7];
    const float* bf  = (const float*)d_in[8];
    const float* A_s = (const float*)d_in[9];
    const float* B_s = (const float*)d_in[10];
    float* out = (float*)d_out;

    cudaFuncSetAttribute(hippo_persistent,
                         cudaFuncAttributeMaxDynamicSharedMemorySize, SM_BYTES);
    hippo_init<<<128, 256>>>(h0, c0);
    hippo_persistent<<<NCTA, NTHR, SM_BYTES>>>(x, Wi, bi, Wh, bh, Wf, bf,
                                               A_s, B_s, out);
}